// round 12
// baseline (speedup 1.0000x reference)
#include <cuda_runtime.h>
#include <cuda_bf16.h>
#include <math.h>
#include <stdint.h>

// Problem constants
#define B_   8192
#define P_   4
#define L_   (B_ * P_)
#define V_   100000
#define D_   128
#define NS_  26
#define NE_  (NS_ + 1)
#define NINT ((NE_ * (NE_ - 1)) / 2)   // 351
#define NFEAT (D_ + NINT)              // 479
#define NFEATP 480

#define NCHUNK 2
#define CHB    (B_ / NCHUNK)           // 4096 rows per chunk

typedef __nv_bfloat16 bf16;

// ---------------- scratch ----------------
__device__ bf16 g_h1b[(size_t)B_ * 512];
__device__ bf16 g_h2b[(size_t)B_ * 256];
__device__ bf16 g_allb[(size_t)B_ * NE_ * D_];
__device__ bf16 g_featb[(size_t)B_ * NFEATP];
__device__ bf16 g_t1b[(size_t)B_ * 512];
__device__ bf16 g_t2b[(size_t)B_ * 256];
__device__ bf16 g_wb2[512 * 256];
__device__ bf16 g_wb3[256 * 128];
__device__ bf16 g_wt1[480 * 512];   // row 479 zeroed
__device__ bf16 g_wt2[512 * 256];

// ---------------- helpers ----------------
__device__ __forceinline__ uint32_t pack_bf16(float a, float b) {
    __nv_bfloat162 h = __floats2bfloat162_rn(a, b);
    return *reinterpret_cast<uint32_t*>(&h);
}
__device__ __forceinline__ void ldsm4(uint32_t& r0, uint32_t& r1, uint32_t& r2, uint32_t& r3,
                                      uint32_t saddr) {
    asm volatile("ldmatrix.sync.aligned.m8n8.x4.shared.b16 {%0,%1,%2,%3}, [%4];"
                 : "=r"(r0), "=r"(r1), "=r"(r2), "=r"(r3) : "r"(saddr));
}
__device__ __forceinline__ void ldsm4t(uint32_t& r0, uint32_t& r1, uint32_t& r2, uint32_t& r3,
                                       uint32_t saddr) {
    asm volatile("ldmatrix.sync.aligned.m8n8.x4.trans.shared.b16 {%0,%1,%2,%3}, [%4];"
                 : "=r"(r0), "=r"(r1), "=r"(r2), "=r"(r3) : "r"(saddr));
}
__device__ __forceinline__ void mma_bf16(float* c, const uint32_t* a, const uint32_t* b) {
    asm volatile(
        "mma.sync.aligned.m16n8k16.row.col.f32.bf16.bf16.f32 "
        "{%0,%1,%2,%3},{%4,%5,%6,%7},{%8,%9},{%0,%1,%2,%3};"
        : "+f"(c[0]), "+f"(c[1]), "+f"(c[2]), "+f"(c[3])
        : "r"(a[0]), "r"(a[1]), "r"(a[2]), "r"(a[3]), "r"(b[0]), "r"(b[1]));
}
__device__ __forceinline__ void cpasync16(uint32_t dst, const void* src) {
    asm volatile("cp.async.cg.shared.global [%0], [%1], 16;" :: "r"(dst), "l"(src));
}
__device__ __forceinline__ void stcs_u2(void* p, uint2 v) {
    asm volatile("st.global.cs.v2.u32 [%0], {%1,%2};" :: "l"(p), "r"(v.x), "r"(v.y) : "memory");
}

// ---------------- weight prep ----------------
__global__ void prep_weights(const float* __restrict__ bw2, const float* __restrict__ bw3,
                             const float* __restrict__ tw1, const float* __restrict__ tw2)
{
    const int S0 = 512 * 256;
    const int S1 = S0 + 256 * 128;
    const int S2 = S1 + 480 * 512;
    const int S3 = S2 + 512 * 256;
    for (int i = blockIdx.x * blockDim.x + threadIdx.x; i < S3; i += gridDim.x * blockDim.x) {
        if (i < S0) {
            g_wb2[i] = __float2bfloat16(bw2[i]);
        } else if (i < S1) {
            int j = i - S0;
            g_wb3[j] = __float2bfloat16(bw3[j]);
        } else if (i < S2) {
            int j = i - S1;
            int k = j >> 9;
            g_wt1[j] = (k < NFEAT) ? __float2bfloat16(tw1[j]) : __float2bfloat16(0.f);
        } else {
            int j = i - S2;
            g_wt2[j] = __float2bfloat16(tw2[j]);
        }
    }
}

// ---------------- embedding bag chunk -> bf16 (table-major within chunk) ----------------
__global__ void embed_kernel(const void* __restrict__ sx_raw,
                             const void* __restrict__ off_raw,
                             const float* __restrict__ tables,
                             int b0)
{
    int g = blockIdx.x * blockDim.x + threadIdx.x;
    int warp = g >> 5;
    int lane = g & 31;
    if (warp >= NS_ * CHB) return;
    int s = warp / CHB;
    int b = b0 + (warp & (CHB - 1));

    const long long* off64 = (const long long*)off_raw;
    const int*       off32 = (const int*)off_raw;
    bool is64 = (off64[1] == (long long)P_);

    long long start, end;
    if (is64) {
        start = off64[b];
        end   = (b + 1 < B_) ? off64[b + 1] : (long long)L_;
    } else {
        start = (long long)off32[b];
        end   = (b + 1 < B_) ? (long long)off32[b + 1] : (long long)L_;
    }

    const long long* sx64 = (const long long*)sx_raw;
    const int*       sx32 = (const int*)sx_raw;
    const float* tb = tables + (size_t)s * V_ * D_;

    float4 acc = make_float4(0.f, 0.f, 0.f, 0.f);
    if ((int)(end - start) == 4) {
        long long i0, i1, i2, i3;
        if (is64) {
            i0 = sx64[(start + 0) * NS_ + s]; i1 = sx64[(start + 1) * NS_ + s];
            i2 = sx64[(start + 2) * NS_ + s]; i3 = sx64[(start + 3) * NS_ + s];
        } else {
            i0 = sx32[(start + 0) * NS_ + s]; i1 = sx32[(start + 1) * NS_ + s];
            i2 = sx32[(start + 2) * NS_ + s]; i3 = sx32[(start + 3) * NS_ + s];
        }
        float4 v0 = __ldg((const float4*)(tb + (size_t)i0 * D_) + lane);
        float4 v1 = __ldg((const float4*)(tb + (size_t)i1 * D_) + lane);
        float4 v2 = __ldg((const float4*)(tb + (size_t)i2 * D_) + lane);
        float4 v3 = __ldg((const float4*)(tb + (size_t)i3 * D_) + lane);
        acc.x = (v0.x + v1.x) + (v2.x + v3.x);
        acc.y = (v0.y + v1.y) + (v2.y + v3.y);
        acc.z = (v0.z + v1.z) + (v2.z + v3.z);
        acc.w = (v0.w + v1.w) + (v2.w + v3.w);
    } else {
        for (long long p = start; p < end; ++p) {
            long long idx = is64 ? sx64[p * NS_ + s] : (long long)sx32[p * NS_ + s];
            float4 v = __ldg((const float4*)(tb + (size_t)idx * D_) + lane);
            acc.x += v.x; acc.y += v.y; acc.z += v.z; acc.w += v.w;
        }
    }
    uint2 val;
    val.x = pack_bf16(acc.x, acc.y);
    val.y = pack_bf16(acc.z, acc.w);
    // streaming store: don't pollute L2 (keep table slice resident)
    stcs_u2(&g_allb[((size_t)b * NE_ + 1 + s) * D_ + lane * 4], val);
}

// ---------------- layer1: dense_x(13) -> 512 ----------------
__global__ __launch_bounds__(256) void layer1_kernel(const float* __restrict__ X,
                                                     const float* __restrict__ W,
                                                     const float* __restrict__ bias)
{
    __shared__ float As[16][13];
    int m0 = blockIdx.x * 16;
    int tid = threadIdx.x;
    if (tid < 16 * 13) As[tid / 13][tid % 13] = X[(size_t)(m0 + tid / 13) * 13 + tid % 13];
    __syncthreads();

    int n0 = tid * 2;
    float w0[13], w1[13];
    #pragma unroll
    for (int k = 0; k < 13; k++) {
        w0[k] = W[k * 512 + n0];
        w1[k] = W[k * 512 + n0 + 1];
    }
    float b0 = bias[n0], b1 = bias[n0 + 1];
    #pragma unroll 4
    for (int r = 0; r < 16; r++) {
        float s0 = b0, s1 = b1;
        #pragma unroll
        for (int k = 0; k < 13; k++) {
            float a = As[r][k];
            s0 += a * w0[k];
            s1 += a * w1[k];
        }
        s0 = fmaxf(s0, 0.f); s1 = fmaxf(s1, 0.f);
        *(uint32_t*)&g_h1b[(size_t)(m0 + r) * 512 + n0] = pack_bf16(s0, s1);
    }
}

// ---------------- templated bf16 GEMM, 3-stage cp.async pipeline ----------------
#define APAD 40

template<int BN, int WMW, int MF, int NF>
__global__ __launch_bounds__(256) void gemm_bf16p(
    const bf16* __restrict__ A,
    const bf16* __restrict__ Wt,
    const float* __restrict__ bias,
    bf16* __restrict__ C,
    int N, int K, int lda, int ldc, int do_relu)
{
    constexpr int BPAD = BN + 8;
    constexpr int CB   = BN / 8;
    constexpr int WMT  = 16 * MF;
    constexpr int WNT  = 8 * NF;

    extern __shared__ unsigned short sm[];
    unsigned short* Asm = sm;
    unsigned short* Bsm = sm + 3 * 128 * APAD;

    const int tid  = threadIdx.x;
    const int warp = tid >> 5;
    const int lane = tid & 31;
    const int wm   = warp % WMW;
    const int wn   = warp / WMW;
    const int g    = lane >> 2;
    const int t    = lane & 3;

    const int bm = blockIdx.y * 128;
    const int bn = blockIdx.x * BN;

    uint32_t sA = (uint32_t)__cvta_generic_to_shared(Asm);
    uint32_t sB = (uint32_t)__cvta_generic_to_shared(Bsm);
    const uint32_t ASTG = 128 * APAD * 2;
    const uint32_t BSTG = 32 * BPAD * 2;

    float acc[MF][NF][4];
    #pragma unroll
    for (int i = 0; i < MF; i++)
        #pragma unroll
        for (int j = 0; j < NF; j++)
            #pragma unroll
            for (int q = 0; q < 4; q++) acc[i][j][q] = 0.f;

    const int nk = K / 32;

    auto prefetch = [&](int kt, int buf) {
        int k0 = kt * 32;
        #pragma unroll
        for (int c = tid; c < 512; c += 256) {
            int r = c >> 2, c8 = (c & 3) * 8;
            cpasync16(sA + buf * ASTG + (uint32_t)(r * APAD + c8) * 2,
                      A + (size_t)(bm + r) * lda + k0 + c8);
        }
        #pragma unroll
        for (int c = tid; c < 32 * CB; c += 256) {
            int r = c / CB, c8 = (c % CB) * 8;
            cpasync16(sB + buf * BSTG + (uint32_t)(r * BPAD + c8) * 2,
                      Wt + (size_t)(k0 + r) * N + bn + c8);
        }
        asm volatile("cp.async.commit_group;" ::: "memory");
    };

    prefetch(0, 0);
    prefetch(1, 1);

    for (int kt = 0; kt < nk; kt++) {
        asm volatile("cp.async.wait_group 1;" ::: "memory");
        __syncthreads();
        if (kt + 2 < nk) prefetch(kt + 2, (kt + 2) % 3);
        else asm volatile("cp.async.commit_group;" ::: "memory");

        uint32_t aBase = sA + (uint32_t)(kt % 3) * ASTG;
        uint32_t bBase = sB + (uint32_t)(kt % 3) * BSTG;

        #pragma unroll
        for (int ks = 0; ks < 2; ks++) {
            const int kk = ks * 16;
            uint32_t a[MF][4];
            #pragma unroll
            for (int fm = 0; fm < MF; fm++) {
                int row = wm * WMT + fm * 16 + (lane & 15);
                uint32_t addr = aBase + (uint32_t)(row * APAD + kk + (lane >> 4) * 8) * 2u;
                ldsm4(a[fm][0], a[fm][1], a[fm][2], a[fm][3], addr);
            }
            uint32_t b[NF][2];
            #pragma unroll
            for (int fn2 = 0; fn2 < NF / 2; fn2++) {
                int krow = kk + (lane & 15);
                int ncol = wn * WNT + fn2 * 16 + (lane >> 4) * 8;
                uint32_t addr = bBase + (uint32_t)(krow * BPAD + ncol) * 2u;
                uint32_t r0, r1, r2, r3;
                ldsm4t(r0, r1, r2, r3, addr);
                b[fn2 * 2][0] = r0;     b[fn2 * 2][1] = r1;
                b[fn2 * 2 + 1][0] = r2; b[fn2 * 2 + 1][1] = r3;
            }
            #pragma unroll
            for (int fm = 0; fm < MF; fm++)
                #pragma unroll
                for (int fn = 0; fn < NF; fn++)
                    mma_bf16(acc[fm][fn], a[fm], b[fn]);
        }
    }

    // epilogue
    #pragma unroll
    for (int fm = 0; fm < MF; fm++) {
        int row0 = bm + wm * WMT + fm * 16 + g;
        #pragma unroll
        for (int fn = 0; fn < NF; fn++) {
            int col0 = bn + wn * WNT + fn * 8 + 2 * t;
            float bv0 = bias[col0], bv1 = bias[col0 + 1];
            float v0 = acc[fm][fn][0] + bv0;
            float v1 = acc[fm][fn][1] + bv1;
            float v2 = acc[fm][fn][2] + bv0;
            float v3 = acc[fm][fn][3] + bv1;
            if (do_relu) {
                v0 = fmaxf(v0, 0.f); v1 = fmaxf(v1, 0.f);
                v2 = fmaxf(v2, 0.f); v3 = fmaxf(v3, 0.f);
            }
            *(uint32_t*)&C[(size_t)row0 * ldc + col0]       = pack_bf16(v0, v1);
            *(uint32_t*)&C[(size_t)(row0 + 8) * ldc + col0] = pack_bf16(v2, v3);
        }
    }
}

// ---------------- interaction via tensor cores (chunk) ----------------
#define IW 4
__global__ __launch_bounds__(128) void interact_mma(const bf16* __restrict__ allb,
                                                    bf16* __restrict__ feat,
                                                    int b0)
{
    __shared__ alignas(16) unsigned short E[IW][32][136];
    int warp = threadIdx.x >> 5;
    int lane = threadIdx.x & 31;
    int b = b0 + blockIdx.x * IW + warp;

    const bf16* src = allb + (size_t)b * NE_ * D_;
    for (int i = lane; i < 27 * 16; i += 32) {
        int r = i >> 4, c8 = (i & 15) * 8;
        *(uint4*)&E[warp][r][c8] = *(const uint4*)(src + r * 128 + c8);
    }
    __syncwarp();

    uint32_t base = (uint32_t)__cvta_generic_to_shared(&E[warp][0][0]);
    float acc[2][4][4];
    #pragma unroll
    for (int i = 0; i < 2; i++)
        #pragma unroll
        for (int j = 0; j < 4; j++)
            #pragma unroll
            for (int q = 0; q < 4; q++) acc[i][j][q] = 0.f;

    #pragma unroll
    for (int ks = 0; ks < 8; ks++) {
        const int kk = ks * 16;
        uint32_t a[2][4];
        #pragma unroll
        for (int fm = 0; fm < 2; fm++) {
            int row = fm * 16 + (lane & 15);
            uint32_t addr = base + (uint32_t)(row * 136 + kk + (lane >> 4) * 8) * 2u;
            ldsm4(a[fm][0], a[fm][1], a[fm][2], a[fm][3], addr);
        }
        uint32_t bf[4][2];
        #pragma unroll
        for (int h = 0; h < 2; h++) {
            bf[h * 2][0]     = a[h][0]; bf[h * 2][1]     = a[h][2];
            bf[h * 2 + 1][0] = a[h][1]; bf[h * 2 + 1][1] = a[h][3];
        }
        #pragma unroll
        for (int fm = 0; fm < 2; fm++)
            #pragma unroll
            for (int fn = 0; fn < 4; fn++)
                mma_bf16(acc[fm][fn], a[fm], bf[fn]);
    }

    bf16* out = feat + (size_t)b * NFEATP;
    *(uint2*)&out[lane * 4] = *(const uint2*)(src + lane * 4);
    if (lane == 0) out[NFEAT] = __float2bfloat16(0.f);

    #pragma unroll
    for (int fm = 0; fm < 2; fm++) {
        int r0 = fm * 16 + (lane >> 2);
        #pragma unroll
        for (int fn = 0; fn < 4; fn++) {
            int c0 = fn * 8 + 2 * (lane & 3);
            float v[4] = {acc[fm][fn][0], acc[fm][fn][1], acc[fm][fn][2], acc[fm][fn][3]};
            #pragma unroll
            for (int q = 0; q < 4; q++) {
                int r = r0 + (q >> 1) * 8;
                int c = c0 + (q & 1);
                if (r < NE_ && c < NE_ && c > r) {
                    int idx = r * NS_ - (r * (r - 1)) / 2 + (c - r - 1);
                    out[D_ + idx] = __float2bfloat16(v[q]);
                }
            }
        }
    }
}

// ---------------- final layer (chunk) ----------------
__global__ void final_kernel(const bf16* __restrict__ t2,
                             const float* __restrict__ w,
                             const float* __restrict__ bias,
                             float* __restrict__ out)
{
    int row = blockIdx.x * (blockDim.x >> 5) + (threadIdx.x >> 5);
    int lane = threadIdx.x & 31;
    if (row >= CHB) return;
    const bf16* x = t2 + (size_t)row * 256;
    float s = 0.f;
    #pragma unroll
    for (int i = lane; i < 256; i += 32) s += __bfloat162float(x[i]) * w[i];
    #pragma unroll
    for (int o = 16; o; o >>= 1) s += __shfl_xor_sync(0xFFFFFFFFu, s, o);
    if (lane == 0) out[row] = 1.f / (1.f + expf(-(s + bias[0])));
}

// ---------------- launch ----------------
extern "C" void kernel_launch(void* const* d_in, const int* in_sizes, int n_in,
                              void* d_out, int out_size)
{
    const float* dense_x   = (const float*)d_in[0];
    const void*  sparse_x  = d_in[1];
    const void*  sparse_of = d_in[2];
    const float* tables    = (const float*)d_in[3];
    const float* bw1 = (const float*)d_in[4];
    const float* bb1 = (const float*)d_in[5];
    const float* bw2 = (const float*)d_in[6];
    const float* bb2 = (const float*)d_in[7];
    const float* bw3 = (const float*)d_in[8];
    const float* bb3 = (const float*)d_in[9];
    const float* tw1 = (const float*)d_in[10];
    const float* tb1 = (const float*)d_in[11];
    const float* tw2 = (const float*)d_in[12];
    const float* tb2 = (const float*)d_in[13];
    const float* tw3 = (const float*)d_in[14];
    const float* tb3 = (const float*)d_in[15];
    float* out = (float*)d_out;

    bf16 *h1b, *h2b, *allb, *featb, *t1b, *t2b, *wb2, *wb3, *wt1, *wt2;
    cudaGetSymbolAddress((void**)&h1b,   g_h1b);
    cudaGetSymbolAddress((void**)&h2b,   g_h2b);
    cudaGetSymbolAddress((void**)&allb,  g_allb);
    cudaGetSymbolAddress((void**)&featb, g_featb);
    cudaGetSymbolAddress((void**)&t1b,   g_t1b);
    cudaGetSymbolAddress((void**)&t2b,   g_t2b);
    cudaGetSymbolAddress((void**)&wb2,   g_wb2);
    cudaGetSymbolAddress((void**)&wb3,   g_wb3);
    cudaGetSymbolAddress((void**)&wt1,   g_wt1);
    cudaGetSymbolAddress((void**)&wt2,   g_wt2);

    constexpr int SM64  = 3 * (128 * APAD + 32 * 72)  * 2;
    constexpr int SM128 = 3 * (128 * APAD + 32 * 136) * 2;
    cudaFuncSetAttribute(gemm_bf16p<64, 4, 2, 4>,  cudaFuncAttributeMaxDynamicSharedMemorySize, SM64);
    cudaFuncSetAttribute(gemm_bf16p<128, 2, 4, 4>, cudaFuncAttributeMaxDynamicSharedMemorySize, SM128);

    // ONE side stream (2nd stream in R11 leaked a 2MB pool); events are cheap
    cudaStream_t sD;
    cudaStreamCreateWithFlags(&sD, cudaStreamNonBlocking);
    cudaEvent_t eFork, eEmb[NCHUNK], eDone;
    cudaEventCreateWithFlags(&eFork, cudaEventDisableTiming);
    cudaEventCreateWithFlags(&eDone, cudaEventDisableTiming);
    for (int c = 0; c < NCHUNK; c++) cudaEventCreateWithFlags(&eEmb[c], cudaEventDisableTiming);

    cudaEventRecord(eFork, 0);
    cudaStreamWaitEvent(sD, eFork, 0);

    // embedding chunks on the MAIN stream (the long pole, starts at t=0)
    {
        int blocks = (NS_ * CHB * 32 + 255) / 256;
        for (int c = 0; c < NCHUNK; c++) {
            embed_kernel<<<blocks, 256>>>(sparse_x, sparse_of, tables, c * CHB);
            cudaEventRecord(eEmb[c], 0);
        }
    }

    // side stream: bottom chain, then per-chunk downstream
    prep_weights<<<256, 256, 0, sD>>>(bw2, bw3, tw1, tw2);
    layer1_kernel<<<B_ / 16, 256, 0, sD>>>(dense_x, bw1, bb1);
    gemm_bf16p<64, 4, 2, 4><<<dim3(4, 64), 256, SM64, sD>>>(h1b, wb2, bb2, h2b, 256, 512, 512, 256, 1);
    gemm_bf16p<64, 4, 2, 4><<<dim3(2, 64), 256, SM64, sD>>>(h2b, wb3, bb3, allb, 128, 256, 256, NE_ * D_, 1);

    for (int c = 0; c < NCHUNK; c++) {
        int b0 = c * CHB;
        cudaStreamWaitEvent(sD, eEmb[c], 0);
        interact_mma<<<CHB / IW, 128, 0, sD>>>(allb, featb, b0);
        gemm_bf16p<128, 2, 4, 4><<<dim3(4, CHB / 128), 256, SM128, sD>>>(
            featb + (size_t)b0 * NFEATP, wt1, tb1, t1b + (size_t)b0 * 512, 512, 480, NFEATP, 512, 1);
        gemm_bf16p<64, 4, 2, 4><<<dim3(4, CHB / 128), 256, SM64, sD>>>(
            t1b + (size_t)b0 * 512, wt2, tb2, t2b + (size_t)b0 * 256, 256, 512, 512, 256, 1);
        final_kernel<<<CHB / 8, 256, 0, sD>>>(t2b + (size_t)b0 * 256, tw3, tb3, out + b0);
    }
    cudaEventRecord(eDone, sD);
    cudaStreamWaitEvent(0, eDone, 0);
}

// round 14
// speedup vs baseline: 1.1770x; 1.1770x over previous
#include <cuda_runtime.h>
#include <cuda_bf16.h>
#include <math.h>
#include <stdint.h>

// Problem constants
#define B_   8192
#define P_   4
#define L_   (B_ * P_)
#define V_   100000
#define D_   128
#define NS_  26
#define NE_  (NS_ + 1)
#define NINT ((NE_ * (NE_ - 1)) / 2)   // 351
#define NFEAT (D_ + NINT)              // 479
#define NFEATP 480

typedef __nv_bfloat16 bf16;

// ---------------- scratch ----------------
__device__ bf16 g_h1b[(size_t)B_ * 512];
__device__ bf16 g_h2b[(size_t)B_ * 256];
__device__ bf16 g_allb[(size_t)B_ * NE_ * D_];
__device__ bf16 g_featb[(size_t)B_ * NFEATP];
__device__ bf16 g_t1b[(size_t)B_ * 512];
__device__ bf16 g_t2b[(size_t)B_ * 256];
__device__ bf16 g_wb2[512 * 256];
__device__ bf16 g_wb3[256 * 128];
__device__ bf16 g_wt1[480 * 512];   // row 479 zeroed
__device__ bf16 g_wt2[512 * 256];

// ---------------- helpers ----------------
__device__ __forceinline__ uint32_t pack_bf16(float a, float b) {
    __nv_bfloat162 h = __floats2bfloat162_rn(a, b);
    return *reinterpret_cast<uint32_t*>(&h);
}
__device__ __forceinline__ void ldsm4(uint32_t& r0, uint32_t& r1, uint32_t& r2, uint32_t& r3,
                                      uint32_t saddr) {
    asm volatile("ldmatrix.sync.aligned.m8n8.x4.shared.b16 {%0,%1,%2,%3}, [%4];"
                 : "=r"(r0), "=r"(r1), "=r"(r2), "=r"(r3) : "r"(saddr));
}
__device__ __forceinline__ void ldsm4t(uint32_t& r0, uint32_t& r1, uint32_t& r2, uint32_t& r3,
                                       uint32_t saddr) {
    asm volatile("ldmatrix.sync.aligned.m8n8.x4.trans.shared.b16 {%0,%1,%2,%3}, [%4];"
                 : "=r"(r0), "=r"(r1), "=r"(r2), "=r"(r3) : "r"(saddr));
}
__device__ __forceinline__ void mma_bf16(float* c, const uint32_t* a, const uint32_t* b) {
    asm volatile(
        "mma.sync.aligned.m16n8k16.row.col.f32.bf16.bf16.f32 "
        "{%0,%1,%2,%3},{%4,%5,%6,%7},{%8,%9},{%0,%1,%2,%3};"
        : "+f"(c[0]), "+f"(c[1]), "+f"(c[2]), "+f"(c[3])
        : "r"(a[0]), "r"(a[1]), "r"(a[2]), "r"(a[3]), "r"(b[0]), "r"(b[1]));
}
__device__ __forceinline__ void cpasync16(uint32_t dst, const void* src) {
    asm volatile("cp.async.cg.shared.global [%0], [%1], 16;" :: "r"(dst), "l"(src));
}
// 32B table load: non-coherent, keep in L2 (evict_last) — v4.b64 form required on sm_103
__device__ __forceinline__ void ldg_el32(const void* p, float* f) {
    unsigned long long a, b, c, d;
    asm volatile("ld.global.nc.L2::evict_last.v4.b64 {%0,%1,%2,%3}, [%4];"
                 : "=l"(a), "=l"(b), "=l"(c), "=l"(d) : "l"(p));
    f[0] = __uint_as_float((uint32_t)a); f[1] = __uint_as_float((uint32_t)(a >> 32));
    f[2] = __uint_as_float((uint32_t)b); f[3] = __uint_as_float((uint32_t)(b >> 32));
    f[4] = __uint_as_float((uint32_t)c); f[5] = __uint_as_float((uint32_t)(c >> 32));
    f[6] = __uint_as_float((uint32_t)d); f[7] = __uint_as_float((uint32_t)(d >> 32));
}
// streaming 16B store (evict-first)
__device__ __forceinline__ void stcs_u4(void* p, uint32_t x, uint32_t y, uint32_t z, uint32_t w) {
    asm volatile("st.global.cs.v4.b32 [%0], {%1,%2,%3,%4};"
                 :: "l"(p), "r"(x), "r"(y), "r"(z), "r"(w) : "memory");
}

// ---------------- weight prep ----------------
__global__ void prep_weights(const float* __restrict__ bw2, const float* __restrict__ bw3,
                             const float* __restrict__ tw1, const float* __restrict__ tw2)
{
    const int S0 = 512 * 256;
    const int S1 = S0 + 256 * 128;
    const int S2 = S1 + 480 * 512;
    const int S3 = S2 + 512 * 256;
    for (int i = blockIdx.x * blockDim.x + threadIdx.x; i < S3; i += gridDim.x * blockDim.x) {
        if (i < S0) {
            g_wb2[i] = __float2bfloat16(bw2[i]);
        } else if (i < S1) {
            int j = i - S0;
            g_wb3[j] = __float2bfloat16(bw3[j]);
        } else if (i < S2) {
            int j = i - S1;
            int k = j >> 9;
            g_wt1[j] = (k < NFEAT) ? __float2bfloat16(tw1[j]) : __float2bfloat16(0.f);
        } else {
            int j = i - S2;
            g_wt2[j] = __float2bfloat16(tw2[j]);
        }
    }
}

// ---------------- embedding bag -> bf16 (table-major, 2 units/warp, 32B loads) ----------------
// Warp w: lanes 0-15 handle unit 2w, lanes 16-31 handle unit 2w+1.
// Unit u: s = u / B, b = u % B (table-major). Each lane loads one 32B chunk
// of the 512B row with evict_last; streaming 16B bf16 store.
__global__ void embed_kernel(const void* __restrict__ sx_raw,
                             const void* __restrict__ off_raw,
                             const float* __restrict__ tables)
{
    int gtid = blockIdx.x * blockDim.x + threadIdx.x;
    int warp = gtid >> 5;
    int lane = gtid & 31;
    int half = lane >> 4;          // 0 or 1
    int hl   = lane & 15;          // chunk index 0..15
    int u = 2 * warp + half;
    if (u >= B_ * NS_) return;
    int s = u >> 13;               // / B_
    int b = u & (B_ - 1);

    const long long* off64 = (const long long*)off_raw;
    const int*       off32 = (const int*)off_raw;
    bool is64 = (off64[1] == (long long)P_);

    long long start, end;
    if (is64) {
        start = off64[b];
        end   = (b + 1 < B_) ? off64[b + 1] : (long long)L_;
    } else {
        start = (long long)off32[b];
        end   = (b + 1 < B_) ? (long long)off32[b + 1] : (long long)L_;
    }

    const long long* sx64 = (const long long*)sx_raw;
    const int*       sx32 = (const int*)sx_raw;
    const float* tb = tables + (size_t)s * V_ * D_;

    float acc[8] = {0.f, 0.f, 0.f, 0.f, 0.f, 0.f, 0.f, 0.f};
    if ((int)(end - start) == 4) {
        long long i0, i1, i2, i3;
        if (is64) {
            i0 = sx64[(start + 0) * NS_ + s]; i1 = sx64[(start + 1) * NS_ + s];
            i2 = sx64[(start + 2) * NS_ + s]; i3 = sx64[(start + 3) * NS_ + s];
        } else {
            i0 = sx32[(start + 0) * NS_ + s]; i1 = sx32[(start + 1) * NS_ + s];
            i2 = sx32[(start + 2) * NS_ + s]; i3 = sx32[(start + 3) * NS_ + s];
        }
        float v0[8], v1[8], v2[8], v3[8];
        ldg_el32((const char*)(tb + (size_t)i0 * D_) + hl * 32, v0);
        ldg_el32((const char*)(tb + (size_t)i1 * D_) + hl * 32, v1);
        ldg_el32((const char*)(tb + (size_t)i2 * D_) + hl * 32, v2);
        ldg_el32((const char*)(tb + (size_t)i3 * D_) + hl * 32, v3);
        #pragma unroll
        for (int q = 0; q < 8; q++) acc[q] = (v0[q] + v1[q]) + (v2[q] + v3[q]);
    } else {
        for (long long p = start; p < end; ++p) {
            long long idx = is64 ? sx64[p * NS_ + s] : (long long)sx32[p * NS_ + s];
            float v[8];
            ldg_el32((const char*)(tb + (size_t)idx * D_) + hl * 32, v);
            #pragma unroll
            for (int q = 0; q < 8; q++) acc[q] += v[q];
        }
    }
    // 8 floats -> 4 bf16 pairs -> one streaming 16B store
    stcs_u4(&g_allb[((size_t)b * NE_ + 1 + s) * D_ + hl * 8],
            pack_bf16(acc[0], acc[1]), pack_bf16(acc[2], acc[3]),
            pack_bf16(acc[4], acc[5]), pack_bf16(acc[6], acc[7]));
}

// ---------------- layer1: dense_x(13) -> 512 ----------------
__global__ __launch_bounds__(256) void layer1_kernel(const float* __restrict__ X,
                                                     const float* __restrict__ W,
                                                     const float* __restrict__ bias)
{
    __shared__ float As[16][13];
    int m0 = blockIdx.x * 16;
    int tid = threadIdx.x;
    if (tid < 16 * 13) As[tid / 13][tid % 13] = X[(size_t)(m0 + tid / 13) * 13 + tid % 13];
    __syncthreads();

    int n0 = tid * 2;
    float w0[13], w1[13];
    #pragma unroll
    for (int k = 0; k < 13; k++) {
        w0[k] = W[k * 512 + n0];
        w1[k] = W[k * 512 + n0 + 1];
    }
    float b0 = bias[n0], b1 = bias[n0 + 1];
    #pragma unroll 4
    for (int r = 0; r < 16; r++) {
        float s0 = b0, s1 = b1;
        #pragma unroll
        for (int k = 0; k < 13; k++) {
            float a = As[r][k];
            s0 += a * w0[k];
            s1 += a * w1[k];
        }
        s0 = fmaxf(s0, 0.f); s1 = fmaxf(s1, 0.f);
        *(uint32_t*)&g_h1b[(size_t)(m0 + r) * 512 + n0] = pack_bf16(s0, s1);
    }
}

// ---------------- templated bf16 GEMM, 3-stage cp.async pipeline ----------------
#define APAD 40

template<int BN, int WMW, int MF, int NF>
__global__ __launch_bounds__(256) void gemm_bf16p(
    const bf16* __restrict__ A,
    const bf16* __restrict__ Wt,
    const float* __restrict__ bias,
    bf16* __restrict__ C,
    int N, int K, int lda, int ldc, int do_relu)
{
    constexpr int BPAD = BN + 8;
    constexpr int CB   = BN / 8;
    constexpr int WMT  = 16 * MF;
    constexpr int WNT  = 8 * NF;

    extern __shared__ unsigned short sm[];
    unsigned short* Asm = sm;
    unsigned short* Bsm = sm + 3 * 128 * APAD;

    const int tid  = threadIdx.x;
    const int warp = tid >> 5;
    const int lane = tid & 31;
    const int wm   = warp % WMW;
    const int wn   = warp / WMW;
    const int g    = lane >> 2;
    const int t    = lane & 3;

    const int bm = blockIdx.y * 128;
    const int bn = blockIdx.x * BN;

    uint32_t sA = (uint32_t)__cvta_generic_to_shared(Asm);
    uint32_t sB = (uint32_t)__cvta_generic_to_shared(Bsm);
    const uint32_t ASTG = 128 * APAD * 2;
    const uint32_t BSTG = 32 * BPAD * 2;

    float acc[MF][NF][4];
    #pragma unroll
    for (int i = 0; i < MF; i++)
        #pragma unroll
        for (int j = 0; j < NF; j++)
            #pragma unroll
            for (int q = 0; q < 4; q++) acc[i][j][q] = 0.f;

    const int nk = K / 32;

    auto prefetch = [&](int kt, int buf) {
        int k0 = kt * 32;
        #pragma unroll
        for (int c = tid; c < 512; c += 256) {
            int r = c >> 2, c8 = (c & 3) * 8;
            cpasync16(sA + buf * ASTG + (uint32_t)(r * APAD + c8) * 2,
                      A + (size_t)(bm + r) * lda + k0 + c8);
        }
        #pragma unroll
        for (int c = tid; c < 32 * CB; c += 256) {
            int r = c / CB, c8 = (c % CB) * 8;
            cpasync16(sB + buf * BSTG + (uint32_t)(r * BPAD + c8) * 2,
                      Wt + (size_t)(k0 + r) * N + bn + c8);
        }
        asm volatile("cp.async.commit_group;" ::: "memory");
    };

    prefetch(0, 0);
    prefetch(1, 1);

    for (int kt = 0; kt < nk; kt++) {
        asm volatile("cp.async.wait_group 1;" ::: "memory");
        __syncthreads();
        if (kt + 2 < nk) prefetch(kt + 2, (kt + 2) % 3);
        else asm volatile("cp.async.commit_group;" ::: "memory");

        uint32_t aBase = sA + (uint32_t)(kt % 3) * ASTG;
        uint32_t bBase = sB + (uint32_t)(kt % 3) * BSTG;

        #pragma unroll
        for (int ks = 0; ks < 2; ks++) {
            const int kk = ks * 16;
            uint32_t a[MF][4];
            #pragma unroll
            for (int fm = 0; fm < MF; fm++) {
                int row = wm * WMT + fm * 16 + (lane & 15);
                uint32_t addr = aBase + (uint32_t)(row * APAD + kk + (lane >> 4) * 8) * 2u;
                ldsm4(a[fm][0], a[fm][1], a[fm][2], a[fm][3], addr);
            }
            uint32_t b[NF][2];
            #pragma unroll
            for (int fn2 = 0; fn2 < NF / 2; fn2++) {
                int krow = kk + (lane & 15);
                int ncol = wn * WNT + fn2 * 16 + (lane >> 4) * 8;
                uint32_t addr = bBase + (uint32_t)(krow * BPAD + ncol) * 2u;
                uint32_t r0, r1, r2, r3;
                ldsm4t(r0, r1, r2, r3, addr);
                b[fn2 * 2][0] = r0;     b[fn2 * 2][1] = r1;
                b[fn2 * 2 + 1][0] = r2; b[fn2 * 2 + 1][1] = r3;
            }
            #pragma unroll
            for (int fm = 0; fm < MF; fm++)
                #pragma unroll
                for (int fn = 0; fn < NF; fn++)
                    mma_bf16(acc[fm][fn], a[fm], b[fn]);
        }
    }

    // epilogue
    #pragma unroll
    for (int fm = 0; fm < MF; fm++) {
        int row0 = bm + wm * WMT + fm * 16 + g;
        #pragma unroll
        for (int fn = 0; fn < NF; fn++) {
            int col0 = bn + wn * WNT + fn * 8 + 2 * t;
            float bv0 = bias[col0], bv1 = bias[col0 + 1];
            float v0 = acc[fm][fn][0] + bv0;
            float v1 = acc[fm][fn][1] + bv1;
            float v2 = acc[fm][fn][2] + bv0;
            float v3 = acc[fm][fn][3] + bv1;
            if (do_relu) {
                v0 = fmaxf(v0, 0.f); v1 = fmaxf(v1, 0.f);
                v2 = fmaxf(v2, 0.f); v3 = fmaxf(v3, 0.f);
            }
            *(uint32_t*)&C[(size_t)row0 * ldc + col0]       = pack_bf16(v0, v1);
            *(uint32_t*)&C[(size_t)(row0 + 8) * ldc + col0] = pack_bf16(v2, v3);
        }
    }
}

// ---------------- interaction via tensor cores ----------------
#define IW 4
__global__ __launch_bounds__(128) void interact_mma(const bf16* __restrict__ allb,
                                                    bf16* __restrict__ feat)
{
    __shared__ alignas(16) unsigned short E[IW][32][136];
    int warp = threadIdx.x >> 5;
    int lane = threadIdx.x & 31;
    int b = blockIdx.x * IW + warp;

    const bf16* src = allb + (size_t)b * NE_ * D_;
    for (int i = lane; i < 27 * 16; i += 32) {
        int r = i >> 4, c8 = (i & 15) * 8;
        *(uint4*)&E[warp][r][c8] = *(const uint4*)(src + r * 128 + c8);
    }
    __syncwarp();

    uint32_t base = (uint32_t)__cvta_generic_to_shared(&E[warp][0][0]);
    float acc[2][4][4];
    #pragma unroll
    for (int i = 0; i < 2; i++)
        #pragma unroll
        for (int j = 0; j < 4; j++)
            #pragma unroll
            for (int q = 0; q < 4; q++) acc[i][j][q] = 0.f;

    #pragma unroll
    for (int ks = 0; ks < 8; ks++) {
        const int kk = ks * 16;
        uint32_t a[2][4];
        #pragma unroll
        for (int fm = 0; fm < 2; fm++) {
            int row = fm * 16 + (lane & 15);
            uint32_t addr = base + (uint32_t)(row * 136 + kk + (lane >> 4) * 8) * 2u;
            ldsm4(a[fm][0], a[fm][1], a[fm][2], a[fm][3], addr);
        }
        uint32_t bf[4][2];
        #pragma unroll
        for (int h = 0; h < 2; h++) {
            bf[h * 2][0]     = a[h][0]; bf[h * 2][1]     = a[h][2];
            bf[h * 2 + 1][0] = a[h][1]; bf[h * 2 + 1][1] = a[h][3];
        }
        #pragma unroll
        for (int fm = 0; fm < 2; fm++)
            #pragma unroll
            for (int fn = 0; fn < 4; fn++)
                mma_bf16(acc[fm][fn], a[fm], bf[fn]);
    }

    bf16* out = feat + (size_t)b * NFEATP;
    *(uint2*)&out[lane * 4] = *(const uint2*)(src + lane * 4);
    if (lane == 0) out[NFEAT] = __float2bfloat16(0.f);

    #pragma unroll
    for (int fm = 0; fm < 2; fm++) {
        int r0 = fm * 16 + (lane >> 2);
        #pragma unroll
        for (int fn = 0; fn < 4; fn++) {
            int c0 = fn * 8 + 2 * (lane & 3);
            float v[4] = {acc[fm][fn][0], acc[fm][fn][1], acc[fm][fn][2], acc[fm][fn][3]};
            #pragma unroll
            for (int q = 0; q < 4; q++) {
                int r = r0 + (q >> 1) * 8;
                int c = c0 + (q & 1);
                if (r < NE_ && c < NE_ && c > r) {
                    int idx = r * NS_ - (r * (r - 1)) / 2 + (c - r - 1);
                    out[D_ + idx] = __float2bfloat16(v[q]);
                }
            }
        }
    }
}

// ---------------- final layer ----------------
__global__ void final_kernel(const bf16* __restrict__ t2,
                             const float* __restrict__ w,
                             const float* __restrict__ bias,
                             float* __restrict__ out)
{
    int row = blockIdx.x * (blockDim.x >> 5) + (threadIdx.x >> 5);
    int lane = threadIdx.x & 31;
    if (row >= B_) return;
    const bf16* x = t2 + (size_t)row * 256;
    float s = 0.f;
    #pragma unroll
    for (int i = lane; i < 256; i += 32) s += __bfloat162float(x[i]) * w[i];
    #pragma unroll
    for (int o = 16; o; o >>= 1) s += __shfl_xor_sync(0xFFFFFFFFu, s, o);
    if (lane == 0) out[row] = 1.f / (1.f + expf(-(s + bias[0])));
}

// ---------------- launch ----------------
extern "C" void kernel_launch(void* const* d_in, const int* in_sizes, int n_in,
                              void* d_out, int out_size)
{
    const float* dense_x   = (const float*)d_in[0];
    const void*  sparse_x  = d_in[1];
    const void*  sparse_of = d_in[2];
    const float* tables    = (const float*)d_in[3];
    const float* bw1 = (const float*)d_in[4];
    const float* bb1 = (const float*)d_in[5];
    const float* bw2 = (const float*)d_in[6];
    const float* bb2 = (const float*)d_in[7];
    const float* bw3 = (const float*)d_in[8];
    const float* bb3 = (const float*)d_in[9];
    const float* tw1 = (const float*)d_in[10];
    const float* tb1 = (const float*)d_in[11];
    const float* tw2 = (const float*)d_in[12];
    const float* tb2 = (const float*)d_in[13];
    const float* tw3 = (const float*)d_in[14];
    const float* tb3 = (const float*)d_in[15];
    float* out = (float*)d_out;

    bf16 *h1b, *h2b, *allb, *featb, *t1b, *t2b, *wb2, *wb3, *wt1, *wt2;
    cudaGetSymbolAddress((void**)&h1b,   g_h1b);
    cudaGetSymbolAddress((void**)&h2b,   g_h2b);
    cudaGetSymbolAddress((void**)&allb,  g_allb);
    cudaGetSymbolAddress((void**)&featb, g_featb);
    cudaGetSymbolAddress((void**)&t1b,   g_t1b);
    cudaGetSymbolAddress((void**)&t2b,   g_t2b);
    cudaGetSymbolAddress((void**)&wb2,   g_wb2);
    cudaGetSymbolAddress((void**)&wb3,   g_wb3);
    cudaGetSymbolAddress((void**)&wt1,   g_wt1);
    cudaGetSymbolAddress((void**)&wt2,   g_wt2);

    constexpr int SM64  = 3 * (128 * APAD + 32 * 72)  * 2;
    constexpr int SM128 = 3 * (128 * APAD + 32 * 136) * 2;
    cudaFuncSetAttribute(gemm_bf16p<64, 4, 2, 4>,  cudaFuncAttributeMaxDynamicSharedMemorySize, SM64);
    cudaFuncSetAttribute(gemm_bf16p<128, 2, 4, 4>, cudaFuncAttributeMaxDynamicSharedMemorySize, SM128);

    // one side stream (R10-proven layout); created per call, capture-safe
    cudaStream_t s1;
    cudaStreamCreateWithFlags(&s1, cudaStreamNonBlocking);
    cudaEvent_t eFork, eJoin;
    cudaEventCreateWithFlags(&eFork, cudaEventDisableTiming);
    cudaEventCreateWithFlags(&eJoin, cudaEventDisableTiming);

    cudaEventRecord(eFork, 0);
    cudaStreamWaitEvent(s1, eFork, 0);

    // embedding flood on the MAIN stream, starts at t=0 (the long pole)
    {
        int nwarps = (B_ * NS_ + 1) / 2;             // 2 units per warp
        int blocks = (nwarps * 32 + 255) / 256;      // 13312
        embed_kernel<<<blocks, 256>>>(sparse_x, sparse_of, tables);
    }

    // bottom chain on the side stream (small grids backfill behind embed)
    prep_weights<<<256, 256, 0, s1>>>(bw2, bw3, tw1, tw2);
    layer1_kernel<<<B_ / 16, 256, 0, s1>>>(dense_x, bw1, bb1);
    gemm_bf16p<64, 4, 2, 4><<<dim3(4, 64), 256, SM64, s1>>>(h1b, wb2, bb2, h2b, 256, 512, 512, 256, 1);
    gemm_bf16p<64, 4, 2, 4><<<dim3(2, 64), 256, SM64, s1>>>(h2b, wb3, bb3, allb, 128, 256, 256, NE_ * D_, 1);
    cudaEventRecord(eJoin, s1);

    // join: interact needs both allb halves (embed on stream 0, chain via eJoin)
    cudaStreamWaitEvent(0, eJoin, 0);
    interact_mma<<<B_ / IW, 128>>>(allb, featb);

    // top MLP
    gemm_bf16p<128, 2, 4, 4><<<dim3(4, 64), 256, SM128>>>(featb, wt1, tb1, t1b, 512, 480, NFEATP, 512, 1);
    gemm_bf16p<64, 4, 2, 4><<<dim3(4, 64), 256, SM64>>>(t1b, wt2, tb2, t2b, 256, 512, 512, 256, 1);

    // final sigmoid
    final_kernel<<<B_ / 8, 256>>>(t2b, tw3, tb3, out);
}